// round 3
// baseline (speedup 1.0000x reference)
#include <cuda_runtime.h>
#include <cuda_fp16.h>
#include <mma.h>
using namespace nvcuda;

#define B_    256
#define TIN   512
#define TOUT  256
#define NSTEP 255

// ---------- device scratch (no allocs) ----------
__device__ __half g_mem16[(size_t)B_*TIN*256];  // fp16 memory
__device__ __half g_keys [(size_t)B_*TIN*256];  // memory @ Wm
__device__ __half g_mema [(size_t)B_*TIN*256];  // memory @ Wa[256:512]
__device__ __half g_W2p[512*1024];              // [Wi[6:]; Wh], cols permuted np=u*4+g
__device__ float  g_zbp[6*1024];                // Wi[v]+b, permuted
__device__ __half g_Wqa[256*512];               // [Wq | Wa[0:256]]
__device__ __half g_Wm16[256*256];
__device__ __half g_Wa2 [256*256];
__device__ __half g_act[2*B_*512];              // [attn(256)|h(256)] double-buffered
__device__ float  g_pqb[B_*512];                // [pq(256)|base(256)]
__device__ float  g_c[B_*256];                  // cell state fp32

__device__ __forceinline__ float sigf(float x){ return 1.f/(1.f+expf(-x)); }
__device__ __forceinline__ float tanh_fast(float x){
  float y; asm("tanh.approx.f32 %0, %1;" : "=f"(y) : "f"(x)); return y;
}

// ---------- prologue ----------
__global__ void prep_small(const float* __restrict__ Wi, const float* __restrict__ Wh,
                           const float* __restrict__ bias, const float* __restrict__ Wm,
                           const float* __restrict__ Wq, const float* __restrict__ Wa,
                           const float* __restrict__ enc_h, const float* __restrict__ enc_c){
  int i = blockIdx.x*256 + threadIdx.x;        // 0..524287
  { int k = i>>10, np = i&1023, u = np>>2, g = np&3, n = g*256+u;
    float w = (k<256) ? Wi[(6+k)*1024+n] : Wh[(k-256)*1024+n];
    g_W2p[i] = __float2half(w); }
  if (i < 6*1024){
    int vv = i>>10, np = i&1023, u = np>>2, g = np&3, n = g*256+u;
    g_zbp[i] = Wi[vv*1024+n] + bias[n]; }
  if (i < 131072){
    int k = i>>9, n = i&511;
    g_Wqa[i] = __float2half(n<256 ? Wq[k*256+n] : Wa[k*256+n-256]); }
  if (i < 65536){
    g_Wm16[i] = __float2half(Wm[i]);
    g_Wa2[i]  = __float2half(Wa[65536+i]);
    g_c[i] = enc_c[i];
    int bb = i>>8, uu = i&255;
    g_act[bb*512+uu]     = __float2half(0.f);
    g_act[bb*512+256+uu] = __float2half(enc_h[i]); }
}

__global__ void prep_big(const float4* __restrict__ mem){
  int i = blockIdx.x*256 + threadIdx.x;        // 8388608 float4
  float4 f = mem[i];
  __half2* o = reinterpret_cast<__half2*>(g_mem16) + (size_t)i*2;
  o[0] = __floats2half2_rn(f.x,f.y);
  o[1] = __floats2half2_rn(f.z,f.w);
}

// C[131072,256] = g_mem16 @ (Wm16 | Wa2)
__global__ void gemm_keys(int which){
  const __half* Bm = which ? g_Wa2 : g_Wm16;
  __half* C        = which ? g_mema : g_keys;
  int wid = threadIdx.x>>5, wm = wid>>1, wn = wid&1;
  size_t m0 = (size_t)blockIdx.y*64 + wm*16;
  int n0 = blockIdx.x*64 + wn*32;
  wmma::fragment<wmma::accumulator,16,16,16,float> a0,a1;
  wmma::fill_fragment(a0,0.f); wmma::fill_fragment(a1,0.f);
  #pragma unroll
  for (int k=0;k<256;k+=16){
    wmma::fragment<wmma::matrix_a,16,16,16,__half,wmma::row_major> a;
    wmma::load_matrix_sync(a, g_mem16 + m0*256 + k, 256);
    wmma::fragment<wmma::matrix_b,16,16,16,__half,wmma::row_major> b0,b1;
    wmma::load_matrix_sync(b0, Bm + k*256 + n0,    256);
    wmma::load_matrix_sync(b1, Bm + k*256 + n0+16, 256);
    wmma::mma_sync(a0,a,b0,a0); wmma::mma_sync(a1,a,b1,a1);
  }
  __shared__ float sm[64][72];
  wmma::store_matrix_sync(&sm[wm*16][wn*32],    a0, 72, wmma::mem_row_major);
  wmma::store_matrix_sync(&sm[wm*16][wn*32+16], a1, 72, wmma::mem_row_major);
  __syncthreads();
  size_t base = (size_t)blockIdx.y*64*256 + blockIdx.x*64;
  for (int i=threadIdx.x;i<64*64;i+=256){
    int r=i>>6, c=i&63;
    C[base + (size_t)r*256 + c] = __float2half(sm[r][c]);
  }
}

// ---------- per-step ----------
__global__ void lstm_step(const int* __restrict__ ids, int step){
  int pr = step&1;
  const __half* actR = g_act + pr*(B_*512);
  __half*       actW = g_act + (pr^1)*(B_*512);
  int wid = threadIdx.x>>5, wm = wid>>1, wn = wid&1;
  int m0 = blockIdx.y*32 + wm*16, n0 = blockIdx.x*64 + wn*32;
  wmma::fragment<wmma::accumulator,16,16,16,float> a0,a1;
  wmma::fill_fragment(a0,0.f); wmma::fill_fragment(a1,0.f);
  #pragma unroll
  for (int k=0;k<512;k+=16){
    wmma::fragment<wmma::matrix_a,16,16,16,__half,wmma::row_major> a;
    wmma::load_matrix_sync(a, actR + m0*512 + k, 512);
    wmma::fragment<wmma::matrix_b,16,16,16,__half,wmma::row_major> b0,b1;
    wmma::load_matrix_sync(b0, g_W2p + k*1024 + n0,    1024);
    wmma::load_matrix_sync(b1, g_W2p + k*1024 + n0+16, 1024);
    wmma::mma_sync(a0,a,b0,a0); wmma::mma_sync(a1,a,b1,a1);
  }
  __shared__ float sm[32][72];
  wmma::store_matrix_sync(&sm[wm*16][wn*32],    a0, 72, wmma::mem_row_major);
  wmma::store_matrix_sync(&sm[wm*16][wn*32+16], a1, 72, wmma::mem_row_major);
  __syncthreads();
  int bbase = blockIdx.y*32, u0 = blockIdx.x*16;
  #pragma unroll
  for (int j=0;j<4;j++){
    int idx = threadIdx.x + j*128;
    int bl = idx>>4, ul = idx&15;
    int bg = bbase+bl, ug = u0+ul;
    int id = ids[bg*TOUT + step];
    const float* zb = g_zbp + id*1024 + blockIdx.x*64 + ul*4;
    float zi = sm[bl][ul*4+0]+zb[0];
    float zf = sm[bl][ul*4+1]+zb[1];
    float zg = sm[bl][ul*4+2]+zb[2];
    float zo = sm[bl][ul*4+3]+zb[3];
    float c  = g_c[bg*256+ug];
    float cn = sigf(zf)*c + sigf(zi)*tanhf(zg);
    float hn = sigf(zo)*tanhf(cn);
    g_c[bg*256+ug] = cn;
    actW[bg*512+256+ug] = __float2half(hn);
  }
}

// [pq|base] = h_new @ [Wq|Wa1]
__global__ void query_step(int step){
  int pr = (step&1)^1;
  const __half* h = g_act + pr*(B_*512) + 256;    // ld 512
  int wid = threadIdx.x>>5, wm = wid>>1, wn = wid&1;
  int m0 = blockIdx.y*64 + wm*16, n0 = blockIdx.x*64 + wn*32;
  wmma::fragment<wmma::accumulator,16,16,16,float> a0,a1;
  wmma::fill_fragment(a0,0.f); wmma::fill_fragment(a1,0.f);
  #pragma unroll
  for (int k=0;k<256;k+=16){
    wmma::fragment<wmma::matrix_a,16,16,16,__half,wmma::row_major> a;
    wmma::load_matrix_sync(a, h + m0*512 + k, 512);
    wmma::fragment<wmma::matrix_b,16,16,16,__half,wmma::row_major> b0,b1;
    wmma::load_matrix_sync(b0, g_Wqa + k*512 + n0,    512);
    wmma::load_matrix_sync(b1, g_Wqa + k*512 + n0+16, 512);
    wmma::mma_sync(a0,a,b0,a0); wmma::mma_sync(a1,a,b1,a1);
  }
  wmma::store_matrix_sync(g_pqb + m0*512 + n0,    a0, 512, wmma::mem_row_major);
  wmma::store_matrix_sync(g_pqb + m0*512 + n0+16, a1, 512, wmma::mem_row_major);
}

// one block per batch: flash-style online softmax folded into attn via mem_a
__global__ void att_step(float* __restrict__ out, const float* __restrict__ v,
                         const float* __restrict__ Wf, const float* __restrict__ bf, int step){
  int b = blockIdx.x;
  int pr = (step&1)^1;
  __half* act = g_act + pr*(B_*512) + b*512;
  __shared__ float s_pq[256], s_v[256], s_base[256], s_attn[256];
  __shared__ float s_ctx[8][256], s_m[8], s_d[8];
  int tid = threadIdx.x, lane = tid&31, w = tid>>5;
  s_pq[tid]   = g_pqb[b*512+tid];
  s_base[tid] = g_pqb[b*512+256+tid];
  s_v[tid]    = v[tid];
  __syncthreads();
  const __half* keys = g_keys + (size_t)b*TIN*256;
  const __half* ma   = g_mema + (size_t)b*TIN*256;
  float m = -1e30f, d = 0.f, C[8];
  #pragma unroll
  for (int k=0;k<8;k++) C[k]=0.f;
  int u0 = lane*8;
  for (int t=w; t<TIN; t+=8){
    uint4 kv = *(const uint4*)(keys + t*256 + u0);
    uint4 mv = *(const uint4*)(ma   + t*256 + u0);
    const __half2* kh = (const __half2*)&kv;
    const __half2* mh = (const __half2*)&mv;
    float mf[8]; float sc = 0.f;
    #pragma unroll
    for (int p=0;p<4;p++){
      float2 kf = __half22float2(kh[p]);
      float2 vf = __half22float2(mh[p]);
      mf[2*p] = vf.x; mf[2*p+1] = vf.y;
      sc += s_v[u0+2*p]   * tanh_fast(kf.x + s_pq[u0+2*p]);
      sc += s_v[u0+2*p+1] * tanh_fast(kf.y + s_pq[u0+2*p+1]);
    }
    #pragma unroll
    for (int o=16;o;o>>=1) sc += __shfl_xor_sync(0xffffffffu, sc, o);
    float mn = fmaxf(m, sc);
    float scale = __expf(m - mn);
    float p = __expf(sc - mn);
    d = d*scale + p;
    #pragma unroll
    for (int k=0;k<8;k++) C[k] = C[k]*scale + p*mf[k];
    m = mn;
  }
  if (lane==0){ s_m[w]=m; s_d[w]=d; }
  __syncthreads();
  float M = s_m[0];
  #pragma unroll
  for (int i=1;i<8;i++) M = fmaxf(M, s_m[i]);
  float D = 0.f;
  #pragma unroll
  for (int i=0;i<8;i++) D += s_d[i]*__expf(s_m[i]-M);
  float r = __expf(m - M);
  #pragma unroll
  for (int k=0;k<8;k++) s_ctx[w][u0+k] = C[k]*r;
  __syncthreads();
  float ctx = 0.f;
  #pragma unroll
  for (int i=0;i<8;i++) ctx += s_ctx[i][tid];
  float attn = s_base[tid] + ctx/D;
  s_attn[tid] = attn;
  act[tid] = __float2half(attn);
  __syncthreads();
  if (w < 6){
    float acc = 0.f;
    for (int u=lane; u<256; u+=32) acc += s_attn[u]*Wf[u*6+w];
    #pragma unroll
    for (int o=16;o;o>>=1) acc += __shfl_xor_sync(0xffffffffu, acc, o);
    if (lane==0) out[((size_t)b*NSTEP + step)*6 + w] = acc + bf[w];
  }
}

extern "C" void kernel_launch(void* const* d_in, const int* in_sizes, int n_in,
                              void* d_out, int out_size){
  const int*   ids    = (const int*)  d_in[0];
  const float* memory = (const float*)d_in[1];
  const float* enc_h  = (const float*)d_in[2];
  const float* enc_c  = (const float*)d_in[3];
  const float* Wi     = (const float*)d_in[4];
  const float* Wh     = (const float*)d_in[5];
  const float* b      = (const float*)d_in[6];
  const float* Wm     = (const float*)d_in[7];
  const float* Wq     = (const float*)d_in[8];
  const float* v      = (const float*)d_in[9];
  const float* Wa     = (const float*)d_in[10];
  const float* Wf     = (const float*)d_in[11];
  const float* bf     = (const float*)d_in[12];
  float* out = (float*)d_out;
  prep_small<<<2048,256>>>(Wi,Wh,b,Wm,Wq,Wa,enc_h,enc_c);
  prep_big<<<32768,256>>>((const float4*)memory);
  dim3 gk(4,2048);
  gemm_keys<<<gk,256>>>(0);
  gemm_keys<<<gk,256>>>(1);
  for (int s=0;s<NSTEP;s++){
    lstm_step<<<dim3(16,8),128>>>(ids, s);
    query_step<<<dim3(8,4),256>>>(s);
    att_step<<<256,256>>>(out, v, Wf, bf, s);
  }
}

// round 6
// speedup vs baseline: 1.9741x; 1.9741x over previous
#include <cuda_runtime.h>
#include <cuda_fp16.h>
#include <mma.h>
using namespace nvcuda;

#define B_    256
#define TIN   512
#define TOUT  256
#define NSTEP 255

// ---------- device scratch (no allocs) ----------
__device__ __half g_mem16[(size_t)B_*TIN*256];  // fp16 memory
__device__ __half g_keys [(size_t)B_*TIN*256];  // memory @ Wm
__device__ __half g_mema [(size_t)B_*TIN*256];  // memory @ Wa[256:512]
__device__ __half g_W2p[512*1024];              // [Wi[6:]; Wh], cols permuted np=u*4+g
__device__ float  g_zbp[6*1024];                // Wi[v]+b, permuted
__device__ __half g_Wqa[256*512];               // [Wq | Wa[0:256]]
__device__ __half g_Wm16[256*256];
__device__ __half g_Wa2 [256*256];
__device__ __half g_act[2*B_*512];              // [attn(256)|h(256)] double-buffered
__device__ float  g_c[B_*256];                  // cell state fp32

__device__ __forceinline__ float sigf(float x){ return 1.f/(1.f+expf(-x)); }
__device__ __forceinline__ float tanh_fast(float x){
  float y; asm("tanh.approx.f32 %0, %1;" : "=f"(y) : "f"(x)); return y;
}

// ---------- prologue ----------
__global__ void prep_small(const float* __restrict__ Wi, const float* __restrict__ Wh,
                           const float* __restrict__ bias, const float* __restrict__ Wm,
                           const float* __restrict__ Wq, const float* __restrict__ Wa,
                           const float* __restrict__ enc_h, const float* __restrict__ enc_c){
  int i = blockIdx.x*256 + threadIdx.x;        // 0..524287
  { int k = i>>10, np = i&1023, u = np>>2, g = np&3, n = g*256+u;
    float w = (k<256) ? Wi[(6+k)*1024+n] : Wh[(k-256)*1024+n];
    g_W2p[i] = __float2half(w); }
  if (i < 6*1024){
    int vv = i>>10, np = i&1023, u = np>>2, g = np&3, n = g*256+u;
    g_zbp[i] = Wi[vv*1024+n] + bias[n]; }
  if (i < 131072){
    int k = i>>9, n = i&511;
    g_Wqa[i] = __float2half(n<256 ? Wq[k*256+n] : Wa[k*256+n-256]); }
  if (i < 65536){
    g_Wm16[i] = __float2half(Wm[i]);
    g_Wa2[i]  = __float2half(Wa[65536+i]);
    g_c[i] = enc_c[i];
    int bb = i>>8, uu = i&255;
    g_act[bb*512+uu]     = __float2half(0.f);
    g_act[bb*512+256+uu] = __float2half(enc_h[i]); }
}

__global__ void prep_big(const float4* __restrict__ mem){
  int i = blockIdx.x*256 + threadIdx.x;        // 8388608 float4
  float4 f = mem[i];
  __half2* o = reinterpret_cast<__half2*>(g_mem16) + (size_t)i*2;
  o[0] = __floats2half2_rn(f.x,f.y);
  o[1] = __floats2half2_rn(f.z,f.w);
}

// C[131072,256] = g_mem16 @ (Wm16 | Wa2), smem-staged. grid (4, 2048, 2), 256 thr.
#define GA_LD 264                 // A pad: 256+8 halves
#define GB_LD 80                  // B pad: 64+16 halves
__global__ void gemm_keys2(){
  extern __shared__ char smc[];
  __half* As = (__half*)smc;                       // 64 x GA_LD
  __half* Bs = (__half*)(smc + 64*GA_LD*2);        // 256 x GB_LD
  float*  epi = (float*)smc;                       // overlay after k-loop: 64 x 72
  int which = blockIdx.z;
  const __half* Bm = which ? g_Wa2 : g_Wm16;
  __half* C        = which ? g_mema : g_keys;
  size_t m0 = (size_t)blockIdx.y*64;
  int n0 = blockIdx.x*64;
  int tid = threadIdx.x;
  // copy A 64x256 (uint4 = 8 halves)
  #pragma unroll
  for (int j=0;j<8;j++){
    int idx = tid + j*256, r = idx>>5, c = idx&31;
    *(uint4*)(As + r*GA_LD + c*8) = *(const uint4*)(g_mem16 + (m0+r)*256 + c*8);
  }
  // copy B 256x64
  #pragma unroll
  for (int j=0;j<8;j++){
    int idx = tid + j*256, r = idx>>3, c = idx&7;
    *(uint4*)(Bs + r*GB_LD + c*8) = *(const uint4*)(Bm + r*256 + n0 + c*8);
  }
  __syncthreads();
  int w = tid>>5, wm = w>>1, wn = w&1;
  wmma::fragment<wmma::accumulator,16,16,16,float> a0,a1;
  wmma::fill_fragment(a0,0.f); wmma::fill_fragment(a1,0.f);
  #pragma unroll
  for (int k=0;k<256;k+=16){
    wmma::fragment<wmma::matrix_a,16,16,16,__half,wmma::row_major> a;
    wmma::load_matrix_sync(a, As + (wm*16)*GA_LD + k, GA_LD);
    wmma::fragment<wmma::matrix_b,16,16,16,__half,wmma::row_major> b0,b1;
    wmma::load_matrix_sync(b0, Bs + k*GB_LD + wn*32,    GB_LD);
    wmma::load_matrix_sync(b1, Bs + k*GB_LD + wn*32+16, GB_LD);
    wmma::mma_sync(a0,a,b0,a0); wmma::mma_sync(a1,a,b1,a1);
  }
  __syncthreads();
  wmma::store_matrix_sync(epi + (wm*16)*72 + wn*32,    a0, 72, wmma::mem_row_major);
  wmma::store_matrix_sync(epi + (wm*16)*72 + wn*32+16, a1, 72, wmma::mem_row_major);
  __syncthreads();
  #pragma unroll
  for (int j=0;j<16;j++){
    int idx = tid + j*256, r = idx>>6, c = idx&63;
    C[(m0+r)*256 + n0 + c] = __float2half(epi[r*72 + c]);
  }
}

// ---------- LSTM step: z = [attn,h]@W2p (+zbp[id]) -> gates. grid (16, 8), 256 thr.
#define LA_LD 520                 // 512+8
#define LB_LD 80                  // 64+16
__global__ void lstm_step(const int* __restrict__ ids, int step){
  extern __shared__ char smc[];
  __half* As = (__half*)smc;                      // 32 x LA_LD
  __half* Bs = (__half*)(smc + 32*LA_LD*2);       // 2 bufs of 64 x LB_LD
  float*  epi = (float*)(smc + 32*LA_LD*2);       // overlay B after k-loop: 32 x 72
  int pr = step&1;
  const __half* actR = g_act + pr*(B_*512);
  __half*       actW = g_act + (pr^1)*(B_*512);
  int tid = threadIdx.x;
  int n0g = blockIdx.x*64, b0 = blockIdx.y*32;
  // copy A 32x512
  #pragma unroll
  for (int j=0;j<8;j++){
    int idx = tid + j*256, r = idx>>6, c = idx&63;
    *(uint4*)(As + r*LA_LD + c*8) = *(const uint4*)(actR + (b0+r)*512 + c*8);
  }
  // prime B chunk 0 (k rows 0..63)
  #pragma unroll
  for (int j=0;j<2;j++){
    int idx = tid + j*256, r = idx>>3, c = idx&7;
    *(uint4*)(Bs + r*LB_LD + c*8) = *(const uint4*)(g_W2p + r*1024 + n0g + c*8);
  }
  __syncthreads();
  int w = tid>>5, wm = w>>2, wn = w&3;    // 2 x 4 warps, each 16x16
  wmma::fragment<wmma::accumulator,16,16,16,float> acc;
  wmma::fill_fragment(acc, 0.f);
  #pragma unroll
  for (int kc=0; kc<8; kc++){
    int cur = kc&1;
    if (kc < 7){
      int nxt = cur^1;
      #pragma unroll
      for (int j=0;j<2;j++){
        int idx = tid + j*256, r = idx>>3, c = idx&7;
        *(uint4*)(Bs + nxt*64*LB_LD + r*LB_LD + c*8) =
          *(const uint4*)(g_W2p + ((kc+1)*64 + r)*1024 + n0g + c*8);
      }
    }
    #pragma unroll
    for (int kk=0; kk<4; kk++){
      wmma::fragment<wmma::matrix_a,16,16,16,__half,wmma::row_major> a;
      wmma::load_matrix_sync(a, As + (wm*16)*LA_LD + kc*64 + kk*16, LA_LD);
      wmma::fragment<wmma::matrix_b,16,16,16,__half,wmma::row_major> b;
      wmma::load_matrix_sync(b, Bs + cur*64*LB_LD + (kk*16)*LB_LD + wn*16, LB_LD);
      wmma::mma_sync(acc, a, b, acc);
    }
    __syncthreads();
  }
  wmma::store_matrix_sync(epi + (wm*16)*72 + wn*16, acc, 72, wmma::mem_row_major);
  __syncthreads();
  #pragma unroll
  for (int j=0;j<2;j++){
    int idx = tid + j*256;                 // 512 (b,u) pairs
    int bl = idx>>4, ul = idx&15;
    int bg = b0+bl, ug = (n0g>>2)+ul;
    int id = ids[bg*TOUT + step];
    const float* zb = g_zbp + id*1024 + n0g + ul*4;
    float zi = epi[bl*72+ul*4+0]+zb[0];
    float zf = epi[bl*72+ul*4+1]+zb[1];
    float zg = epi[bl*72+ul*4+2]+zb[2];
    float zo = epi[bl*72+ul*4+3]+zb[3];
    float c  = g_c[bg*256+ug];
    float cn = sigf(zf)*c + sigf(zi)*tanhf(zg);
    float hn = sigf(zo)*tanhf(cn);
    g_c[bg*256+ug] = cn;
    actW[bg*512+256+ug] = __float2half(hn);
  }
}

// ---------- attention step (query fused). grid 256, 512 thr.
__global__ void att_step(float* __restrict__ out, const float* __restrict__ v,
                         const float* __restrict__ Wf, const float* __restrict__ bf, int step){
  int b = blockIdx.x;
  int pr = (step&1)^1;
  __half* act = g_act + pr*(B_*512) + b*512;
  __shared__ float s_h[256], s_pq[256], s_base[256], s_v[256], s_attn[256];
  __shared__ float s_ctx[16][256], s_m[16], s_d[16];
  int tid = threadIdx.x, lane = tid&31, w = tid>>5;
  if (tid < 256){ s_h[tid] = __half2float(act[256+tid]); s_v[tid] = v[tid]; }
  __syncthreads();
  // query: [pq|base] = h @ [Wq|Wa1]
  { float acc = 0.f;
    #pragma unroll 8
    for (int k=0;k<256;k++) acc += s_h[k]*__half2float(g_Wqa[k*512 + tid]);
    if (tid < 256) s_pq[tid] = acc; else s_base[tid-256] = acc; }
  __syncthreads();
  const __half* keys = g_keys + (size_t)b*TIN*256;
  const __half* ma   = g_mema + (size_t)b*TIN*256;
  int u0 = lane*8;
  float pq_r[8], v_r[8];
  #pragma unroll
  for (int k=0;k<8;k++){ pq_r[k] = s_pq[u0+k]; v_r[k] = s_v[u0+k]; }
  float m = -1e30f, d = 0.f, C[8];
  #pragma unroll
  for (int k=0;k<8;k++) C[k]=0.f;
  int t = w;
  uint4 kv = *(const uint4*)(keys + t*256 + u0);
  uint4 mv = *(const uint4*)(ma   + t*256 + u0);
  #pragma unroll 2
  for (int i=0;i<32;i++){
    uint4 kc = kv, mc = mv;
    int tn = t + 16;
    if (i < 31){
      kv = *(const uint4*)(keys + tn*256 + u0);
      mv = *(const uint4*)(ma   + tn*256 + u0);
    }
    const __half2* kh = (const __half2*)&kc;
    const __half2* mh = (const __half2*)&mc;
    float mf[8]; float sc = 0.f;
    #pragma unroll
    for (int p=0;p<4;p++){
      float2 kf = __half22float2(kh[p]);
      float2 vf = __half22float2(mh[p]);
      mf[2*p] = vf.x; mf[2*p+1] = vf.y;
      sc += v_r[2*p]   * tanh_fast(kf.x + pq_r[2*p]);
      sc += v_r[2*p+1] * tanh_fast(kf.y + pq_r[2*p+1]);
    }
    #pragma unroll
    for (int o=16;o;o>>=1) sc += __shfl_xor_sync(0xffffffffu, sc, o);
    float mn = fmaxf(m, sc);
    float scale = __expf(m - mn);
    float p = __expf(sc - mn);
    d = d*scale + p;
    #pragma unroll
    for (int k=0;k<8;k++) C[k] = C[k]*scale + p*mf[k];
    m = mn;
    t = tn;
  }
  if (lane==0){ s_m[w]=m; s_d[w]=d; }
  __syncthreads();
  float M = s_m[0];
  #pragma unroll
  for (int i=1;i<16;i++) M = fmaxf(M, s_m[i]);
  float D = 0.f;
  #pragma unroll
  for (int i=0;i<16;i++) D += s_d[i]*__expf(s_m[i]-M);
  float r = __expf(m - M);
  #pragma unroll
  for (int k=0;k<8;k++) s_ctx[w][u0+k] = C[k]*r;
  __syncthreads();
  if (tid < 256){
    float ctx = 0.f;
    #pragma unroll
    for (int i=0;i<16;i++) ctx += s_ctx[i][tid];
    float attn = s_base[tid] + ctx/D;
    s_attn[tid] = attn;
    act[tid] = __float2half(attn);
  }
  __syncthreads();
  if (w < 6){
    float acc = 0.f;
    #pragma unroll
    for (int u=lane; u<256; u+=32) acc += s_attn[u]*Wf[u*6+w];
    #pragma unroll
    for (int o=16;o;o>>=1) acc += __shfl_xor_sync(0xffffffffu, acc, o);
    if (lane==0) out[((size_t)b*NSTEP + step)*6 + w] = acc + bf[w];
  }
}

extern "C" void kernel_launch(void* const* d_in, const int* in_sizes, int n_in,
                              void* d_out, int out_size){
  const int*   ids    = (const int*)  d_in[0];
  const float* memory = (const float*)d_in[1];
  const float* enc_h  = (const float*)d_in[2];
  const float* enc_c  = (const float*)d_in[3];
  const float* Wi     = (const float*)d_in[4];
  const float* Wh     = (const float*)d_in[5];
  const float* b      = (const float*)d_in[6];
  const float* Wm     = (const float*)d_in[7];
  const float* Wq     = (const float*)d_in[8];
  const float* v      = (const float*)d_in[9];
  const float* Wa     = (const float*)d_in[10];
  const float* Wf     = (const float*)d_in[11];
  const float* bf     = (const float*)d_in[12];
  float* out = (float*)d_out;

  const int gk_smem = 64*GA_LD*2 + 256*GB_LD*2;         // ~75 KB
  const int ls_smem = 32*LA_LD*2 + 2*64*LB_LD*2;        // ~54 KB
  static int attr_done = 0;
  if (!attr_done){
    cudaFuncSetAttribute(gemm_keys2, cudaFuncAttributeMaxDynamicSharedMemorySize, gk_smem);
    cudaFuncSetAttribute(lstm_step,  cudaFuncAttributeMaxDynamicSharedMemorySize, ls_smem);
    attr_done = 1;
  }
  prep_small<<<2048,256>>>(Wi,Wh,b,Wm,Wq,Wa,enc_h,enc_c);
  prep_big<<<32768,256>>>((const float4*)memory);
  gemm_keys2<<<dim3(4,2048,2),256,gk_smem>>>();
  for (int s=0;s<NSTEP;s++){
    lstm_step<<<dim3(16,8),256,ls_smem>>>(ids, s);
    att_step<<<256,512>>>(out, v, Wf, bf, s);
  }
}